// round 7
// baseline (speedup 1.0000x reference)
#include <cuda_runtime.h>
#include <math.h>
#include <stdint.h>

#define N_NODES 50000
#define N_EDGES 500000
#define DIM 128
#define BN_EPS 1e-5f

#define BLK_M 64
#define AS_STRIDE 36     // 64 rows x 32 k, padded
#define WS_STRIDE 136    // 32 k x 128 cols, padded
#define CS_STRIDE 136    // 32 rows x 128 cols, padded
#define SMEM_FLOATS (BLK_M * AS_STRIDE + 32 * WS_STRIDE)   // 6656 floats = 26624 B

// ---------------- scratch (device globals; no allocations allowed) ----------
__device__ float g_AX[N_NODES * DIM];
__device__ float g_BX[N_NODES * DIM];
__device__ float g_DX[N_NODES * DIM];
__device__ float g_EX[N_NODES * DIM];
__device__ float g_num[N_NODES * DIM];
__device__ float g_den[N_NODES * DIM];
__device__ float g_deg[N_NODES];
__device__ float g_hsum[DIM];
__device__ float g_hsq[DIM];
__device__ float g_esum[DIM];
__device__ float g_esq[DIM];

// ---------------- helpers ----------------------------------------------------
__device__ __forceinline__ void red_add_v4(float* addr, float a, float b, float c, float d) {
    asm volatile("red.global.add.v4.f32 [%0], {%1, %2, %3, %4};"
                 :: "l"(addr), "f"(a), "f"(b), "f"(c), "f"(d)
                 : "memory");
}

__device__ __forceinline__ uint32_t f2tf32(float x) {
    uint32_t r;
    asm("cvt.rna.tf32.f32 %0, %1;" : "=r"(r) : "f"(x));
    return r;
}

__device__ __forceinline__ void mma_tf32(float c[4],
                                         uint32_t a0, uint32_t a1, uint32_t a2, uint32_t a3,
                                         uint32_t b0, uint32_t b1) {
    asm volatile("mma.sync.aligned.m16n8k8.row.col.f32.tf32.tf32.f32 "
                 "{%0,%1,%2,%3},{%4,%5,%6,%7},{%8,%9},{%0,%1,%2,%3};"
                 : "+f"(c[0]), "+f"(c[1]), "+f"(c[2]), "+f"(c[3])
                 : "r"(a0), "r"(a1), "r"(a2), "r"(a3), "r"(b0), "r"(b1));
}

// ================================================================================
// TF32 tensor-core GEMM core (R4-proven): 64x128 tile, 256 threads, 8 warps
// (4 row groups x 2 col groups). Warp covers 16 rows x 64 cols: acc[8][4].
// ================================================================================
__device__ __forceinline__ void gemm_tc64(const float* __restrict__ A, const float* __restrict__ W,
                                          int rowBase, int M, float* As, float* Ws,
                                          float acc[8][4], int tid) {
    int lane = tid & 31, wid = tid >> 5;
    int wr = wid & 3, wc = wid >> 2;
    uint32_t* Asu = (uint32_t*)As;
    uint32_t* Wsu = (uint32_t*)Ws;

    #pragma unroll
    for (int t = 0; t < 8; t++)
        #pragma unroll
        for (int j = 0; j < 4; j++) acc[t][j] = 0.f;

    #pragma unroll
    for (int k0 = 0; k0 < 128; k0 += 32) {
        // stage A tile (64 x 32) with tf32 rounding: 512 float4 = 2/thread
        #pragma unroll
        for (int u = 0; u < 2; u++) {
            int idx = tid + u * 256;            // 0..511
            int r = idx >> 3;
            int c4 = (idx & 7) * 4;
            int gr = min(rowBase + r, M - 1);
            float4 v = *(const float4*)&A[(long)gr * 128 + k0 + c4];
            Asu[r * AS_STRIDE + c4 + 0] = f2tf32(v.x);
            Asu[r * AS_STRIDE + c4 + 1] = f2tf32(v.y);
            Asu[r * AS_STRIDE + c4 + 2] = f2tf32(v.z);
            Asu[r * AS_STRIDE + c4 + 3] = f2tf32(v.w);
        }
        // stage W tile (32 x 128): 1024 float4 = 4/thread
        #pragma unroll
        for (int u = 0; u < 4; u++) {
            int idx = tid + u * 256;
            int kk = idx >> 5;
            int c4 = (idx & 31) * 4;
            float4 v = *(const float4*)&W[(long)(k0 + kk) * 128 + c4];
            Wsu[kk * WS_STRIDE + c4 + 0] = f2tf32(v.x);
            Wsu[kk * WS_STRIDE + c4 + 1] = f2tf32(v.y);
            Wsu[kk * WS_STRIDE + c4 + 2] = f2tf32(v.z);
            Wsu[kk * WS_STRIDE + c4 + 3] = f2tf32(v.w);
        }
        __syncthreads();
        #pragma unroll
        for (int ks = 0; ks < 4; ks++) {
            int kb = ks * 8;
            int r = wr * 16 + (lane >> 2);
            uint32_t a0 = Asu[r * AS_STRIDE + kb + (lane & 3)];
            uint32_t a1 = Asu[(r + 8) * AS_STRIDE + kb + (lane & 3)];
            uint32_t a2 = Asu[r * AS_STRIDE + kb + 4 + (lane & 3)];
            uint32_t a3 = Asu[(r + 8) * AS_STRIDE + kb + 4 + (lane & 3)];
            #pragma unroll
            for (int t = 0; t < 8; t++) {
                int cn = wc * 64 + t * 8 + (lane >> 2);
                uint32_t b0 = Wsu[(kb + (lane & 3)) * WS_STRIDE + cn];
                uint32_t b1 = Wsu[(kb + 4 + (lane & 3)) * WS_STRIDE + cn];
                mma_tf32(acc[t], a0, a1, a2, a3, b0, b1);
            }
        }
        __syncthreads();
    }
}

// store the warp's rows belonging to [h32*32, h32*32+32) into Cs[32][CS_STRIDE]
__device__ __forceinline__ void store_half32(float* Cs, float acc[8][4], int h32, int tid) {
    int lane = tid & 31, wid = tid >> 5;
    int wr = wid & 3, wc = wid >> 2;
    if ((wr >> 1) == h32) {
        int lr = (wr & 1) * 16 + (lane >> 2);
        #pragma unroll
        for (int t = 0; t < 8; t++) {
            int c = wc * 64 + t * 8 + 2 * (lane & 3);
            *(float2*)&Cs[lr * CS_STRIDE + c]       = make_float2(acc[t][0], acc[t][1]);
            *(float2*)&Cs[(lr + 8) * CS_STRIDE + c] = make_float2(acc[t][2], acc[t][3]);
        }
    }
}

// ---------------- zero scratch ------------------------------------------------
__global__ void zero_scratch(float4* num4, float4* den4, float* deg,
                             float* hsum, float* hsq, float* esum, float* esq) {
    int i = blockIdx.x * blockDim.x + threadIdx.x;   // exactly N*D/4 threads
    float4 z = make_float4(0.f, 0.f, 0.f, 0.f);
    num4[i] = z;
    den4[i] = z;
    if (i < N_NODES) deg[i] = 0.f;
    if (i < DIM) { hsum[i] = 0.f; hsq[i] = 0.f; esum[i] = 0.f; esq[i] = 0.f; }
}

// ---------------- degree ------------------------------------------------------
__global__ void deg_kernel(const int* __restrict__ dst, float* __restrict__ deg) {
    int i = blockIdx.x * blockDim.x + threadIdx.x;
    if (i < N_EDGES) atomicAdd(&deg[dst[i]], 1.f);
}

// ---------------- fused node GEMMs (tensor core) --------------------------------
__global__ __launch_bounds__(256, 3)
void gemm_bias(const float* __restrict__ A,
               const float* __restrict__ W0, const float* __restrict__ b0, float* __restrict__ o0,
               const float* __restrict__ W1, const float* __restrict__ b1, float* __restrict__ o1,
               const float* __restrict__ W2, const float* __restrict__ b2, float* __restrict__ o2,
               const float* __restrict__ W3, const float* __restrict__ b3, float* __restrict__ o3,
               int M) {
    __shared__ float smem[SMEM_FLOATS];
    float* As = smem;
    float* Ws = smem + BLK_M * AS_STRIDE;
    float* Cs = smem;   // alias, used after GEMM (32 x CS_STRIDE fits)

    const float *W, *bias;
    float* out;
    switch (blockIdx.y) {
        case 0:  W = W0; bias = b0; out = o0; break;
        case 1:  W = W1; bias = b1; out = o1; break;
        case 2:  W = W2; bias = b2; out = o2; break;
        default: W = W3; bias = b3; out = o3; break;
    }
    int tid = threadIdx.x;
    int rowBase = blockIdx.x * BLK_M;

    float acc[8][4];
    gemm_tc64(A, W, rowBase, M, As, Ws, acc, tid);

    #pragma unroll
    for (int h32 = 0; h32 < 2; h32++) {
        store_half32(Cs, acc, h32, tid);
        __syncthreads();
        int r = tid >> 3, q = tid & 7;
        int grow = rowBase + h32 * 32 + r;
        if (grow < M) {
            #pragma unroll
            for (int cb = 0; cb < 4; cb++) {
                int c = q * 16 + cb * 4;
                float4 v = *(float4*)&Cs[r * CS_STRIDE + c];
                float4 bb = __ldg((const float4*)&bias[c]);
                v.x += bb.x; v.y += bb.y; v.z += bb.z; v.w += bb.w;
                *(float4*)&out[(long)grow * 128 + c] = v;
            }
        }
        __syncthreads();
    }
}

// ---------------- fused edge kernel (tensor core + fused E stats) ---------------
__global__ __launch_bounds__(256, 3)
void edge_kernel(const float* __restrict__ EXin, const float* __restrict__ W,
                 const float* __restrict__ bias,
                 const int* __restrict__ src, const int* __restrict__ dst,
                 const float* __restrict__ sne,
                 const float* __restrict__ BX, const float* __restrict__ DXn,
                 const float* __restrict__ EXn,
                 float* __restrict__ num, float* __restrict__ den,
                 float* __restrict__ outE,
                 float* __restrict__ esum, float* __restrict__ esq) {
    __shared__ float smem[SMEM_FLOATS];
    __shared__ int   s_src[BLK_M];
    __shared__ int   s_dst[BLK_M];
    __shared__ float s_sn[BLK_M];
    __shared__ float sm1[128];
    __shared__ float sm2[128];
    float* As = smem;
    float* Ws = smem + BLK_M * AS_STRIDE;
    float* Cs = smem;

    int tid = threadIdx.x;
    int rowBase = blockIdx.x * BLK_M;

    if (tid < BLK_M) {
        int e = min(rowBase + tid, N_EDGES - 1);
        s_src[tid] = src[e];
        s_dst[tid] = dst[e];
        s_sn[tid]  = sne[e];
    }
    if (tid < 128) { sm1[tid] = 0.f; sm2[tid] = 0.f; }

    float acc[8][4];
    gemm_tc64(EXin, W, rowBase, N_EDGES, As, Ws, acc, tid);

    #pragma unroll
    for (int h32 = 0; h32 < 2; h32++) {
        store_half32(Cs, acc, h32, tid);
        __syncthreads();
        int r = tid >> 3, q = tid & 7;
        long e = (long)rowBase + h32 * 32 + r;
        if (e < N_EDGES) {
            int sv = s_src[h32 * 32 + r];
            int dv = s_dst[h32 * 32 + r];
            float sn = s_sn[h32 * 32 + r];
            const float* dxp = &DXn[(long)sv * 128];
            const float* exp_ = &EXn[(long)dv * 128];
            const float* bxp = &BX[(long)sv * 128];
            float* np = &num[(long)dv * 128];
            float* dp = &den[(long)dv * 128];
            float* op = &outE[e * 128];
            #pragma unroll
            for (int cb = 0; cb < 4; cb++) {
                int c = q * 16 + cb * 4;
                float4 ce = *(float4*)&Cs[r * CS_STRIDE + c];
                float4 bb = __ldg((const float4*)&bias[c]);
                float4 dx = *(const float4*)&dxp[c];
                float4 ex = *(const float4*)&exp_[c];
                float4 bx = *(const float4*)&bxp[c];
                float ej[4] = {ce.x + bb.x + dx.x + ex.x,
                               ce.y + bb.y + dx.y + ex.y,
                               ce.z + bb.z + dx.z + ex.z,
                               ce.w + bb.w + dx.w + ex.w};
                float sg[4], nb[4], ep[4];
                #pragma unroll
                for (int j = 0; j < 4; j++) {
                    ep[j] = ej[j] * sn;
                    sg[j] = 1.f / (1.f + __expf(-ej[j]));
                }
                nb[0] = sg[0] * bx.x; nb[1] = sg[1] * bx.y;
                nb[2] = sg[2] * bx.z; nb[3] = sg[3] * bx.w;
                // streaming store: keep L2 for gathers/atomics
                __stcs((float4*)&op[c], make_float4(ep[0], ep[1], ep[2], ep[3]));
                red_add_v4(np + c, nb[0], nb[1], nb[2], nb[3]);
                red_add_v4(dp + c, sg[0], sg[1], sg[2], sg[3]);
                // fused E column stats (smem accumulate)
                #pragma unroll
                for (int j = 0; j < 4; j++) {
                    atomicAdd(&sm1[c + j], ep[j]);
                    atomicAdd(&sm2[c + j], ep[j] * ep[j]);
                }
            }
        }
        __syncthreads();
    }

    // flush block-level stats to global
    if (tid < 128) {
        atomicAdd(&esum[tid], sm1[tid]);
        atomicAdd(&esq[tid],  sm2[tid]);
    }
}

// ---------------- node pre-BN: Hpre = gate-combine * snorm_n + stats ------------
__global__ void node_pre(const float* __restrict__ X, const float* __restrict__ AX,
                         const float* __restrict__ num, const float* __restrict__ den,
                         const float* __restrict__ deg, const float* __restrict__ snorm_n,
                         float* __restrict__ outH,
                         float* __restrict__ hsum, float* __restrict__ hsq) {
    __shared__ float sm1[128];
    __shared__ float sm2[128];
    int tid = threadIdx.x;
    if (tid < 128) { sm1[tid] = 0.f; sm2[tid] = 0.f; }
    __syncthreads();

    int c = tid & 127;
    int half = tid >> 7;
    int rBase = blockIdx.x * 64;
    int rEnd = min(rBase + 64, N_NODES);

    float s1 = 0.f, s2 = 0.f;
    for (int r = rBase + half; r < rEnd; r += 2) {
        float dg = deg[r];
        float sn = snorm_n[r];
        long idx = (long)r * 128 + c;
        float hv;
        if (dg > 0.f) {
            float dn = den[idx];
            float qv = (dn > 0.f) ? (num[idx] / dn) : 0.f;
            hv = AX[idx] + qv;
        } else {
            hv = X[idx];
        }
        hv *= sn;
        outH[idx] = hv;
        s1 += hv;
        s2 += hv * hv;
    }
    atomicAdd(&sm1[c], s1);
    atomicAdd(&sm2[c], s2);
    __syncthreads();
    if (tid < 128) atomicAdd(&hsum[tid], sm1[tid]);
    else           atomicAdd(&hsq[tid - 128], sm2[tid - 128]);
}

// ---------------- finalize: out = base + relu(BN(pre)) (in-place over pre) ------
__global__ void finalize_bn(const float* __restrict__ base, float* __restrict__ pre,
                            const float* __restrict__ sum, const float* __restrict__ sq,
                            const float* __restrict__ gamma, const float* __restrict__ beta,
                            long total4, float invn) {
    long i = (long)blockIdx.x * blockDim.x + threadIdx.x;
    if (i >= total4) return;
    int c4 = (int)(i & 31) * 4;
    float4 v  = __ldcs(&((const float4*)pre)[i]);
    float4 xv = __ldcs(&((const float4*)base)[i]);
    float vv[4] = {v.x, v.y, v.z, v.w};
    float xx[4] = {xv.x, xv.y, xv.z, xv.w};
    float oo[4];
    #pragma unroll
    for (int j = 0; j < 4; j++) {
        int c = c4 + j;
        float m   = __ldg(&sum[c]) * invn;
        float var = __ldg(&sq[c]) * invn - m * m;
        float rs  = rsqrtf(var + BN_EPS);
        float t = (vv[j] - m) * rs * __ldg(&gamma[c]) + __ldg(&beta[c]);
        oo[j] = xx[j] + fmaxf(t, 0.f);
    }
    __stcs(&((float4*)pre)[i], make_float4(oo[0], oo[1], oo[2], oo[3]));
}

// ---------------- launch --------------------------------------------------------
extern "C" void kernel_launch(void* const* d_in, const int* in_sizes, int n_in,
                              void* d_out, int out_size) {
    const float* X       = (const float*)d_in[0];
    const float* E_X     = (const float*)d_in[1];
    const int*   src     = (const int*)  d_in[2];
    const int*   dst     = (const int*)  d_in[3];
    const float* snorm_n = (const float*)d_in[4];
    const float* snorm_e = (const float*)d_in[5];
    const float* WA = (const float*)d_in[6];
    const float* bA = (const float*)d_in[7];
    const float* WB = (const float*)d_in[8];
    const float* bB = (const float*)d_in[9];
    const float* WC = (const float*)d_in[10];
    const float* bC = (const float*)d_in[11];
    const float* WD = (const float*)d_in[12];
    const float* bD = (const float*)d_in[13];
    const float* WE = (const float*)d_in[14];
    const float* bE = (const float*)d_in[15];
    const float* gamma_h = (const float*)d_in[16];
    const float* beta_h  = (const float*)d_in[17];
    const float* gamma_e = (const float*)d_in[18];
    const float* beta_e  = (const float*)d_in[19];

    float* out  = (float*)d_out;
    float* outH = out;
    float* outE = out + (long)N_NODES * DIM;

    float *pAX, *pBX, *pDX, *pEX, *pnum, *pden, *pdeg;
    float *phsum, *phsq, *pesum, *pesq;
    cudaGetSymbolAddress((void**)&pAX, g_AX);
    cudaGetSymbolAddress((void**)&pBX, g_BX);
    cudaGetSymbolAddress((void**)&pDX, g_DX);
    cudaGetSymbolAddress((void**)&pEX, g_EX);
    cudaGetSymbolAddress((void**)&pnum, g_num);
    cudaGetSymbolAddress((void**)&pden, g_den);
    cudaGetSymbolAddress((void**)&pdeg, g_deg);
    cudaGetSymbolAddress((void**)&phsum, g_hsum);
    cudaGetSymbolAddress((void**)&phsq, g_hsq);
    cudaGetSymbolAddress((void**)&pesum, g_esum);
    cudaGetSymbolAddress((void**)&pesq, g_esq);

    // 1. zero scratch
    zero_scratch<<<6250, 256>>>((float4*)pnum, (float4*)pden, pdeg,
                                phsum, phsq, pesum, pesq);

    // 2. node GEMMs (tensor core, fused: grid.y selects A/B/D/E weights)
    dim3 ngrid((N_NODES + BLK_M - 1) / BLK_M, 4);   // 782 x 4
    gemm_bias<<<ngrid, 256>>>(X,
                              WA, bA, pAX,
                              WB, bB, pBX,
                              WD, bD, pDX,
                              WE, bE, pEX,
                              N_NODES);

    // 3. degrees
    deg_kernel<<<(N_EDGES + 255) / 256, 256>>>(dst, pdeg);

    // 4. fused edge kernel (CE GEMM + message + gated scatter + E stats)
    int edgeBlocks = (N_EDGES + BLK_M - 1) / BLK_M;   // 7813
    edge_kernel<<<edgeBlocks, 256>>>(E_X, WC, bC, src, dst, snorm_e,
                                     pBX, pDX, pEX, pnum, pden, outE,
                                     pesum, pesq);

    // 5. node combine + H stats
    node_pre<<<(N_NODES + 63) / 64, 256>>>(X, pAX, pnum, pden, pdeg, snorm_n,
                                           outH, phsum, phsq);

    // 6. finalize H: out = X + relu(BN(Hpre))
    long h4 = (long)N_NODES * DIM / 4;       // 1.6M
    finalize_bn<<<(int)((h4 + 255) / 256), 256>>>(X, outH, phsum, phsq,
                                                  gamma_h, beta_h, h4, 1.f / N_NODES);

    // 7. finalize E: out = E_X + relu(BN(Epre))
    long e4 = (long)N_EDGES * DIM / 4;       // 16M
    finalize_bn<<<(int)((e4 + 255) / 256), 256>>>(E_X, outE, pesum, pesq,
                                                  gamma_e, beta_e, e4, 1.f / N_EDGES);
}

// round 8
// speedup vs baseline: 1.8577x; 1.8577x over previous
#include <cuda_runtime.h>
#include <math.h>
#include <stdint.h>

#define N_NODES 50000
#define N_EDGES 500000
#define DIM 128
#define BN_EPS 1e-5f

#define BLK_M 64
#define AS_STRIDE 36     // 64 rows x 32 k, padded
#define WS_STRIDE 136    // 32 k x 128 cols, padded
#define CS_STRIDE 136    // 32 rows x 128 cols, padded
#define SMEM_FLOATS (BLK_M * AS_STRIDE + 32 * WS_STRIDE)   // 6656 floats = 26624 B

// ---------------- scratch (device globals; no allocations allowed) ----------
__device__ float g_AX[N_NODES * DIM];
__device__ float g_BX[N_NODES * DIM];
__device__ float g_DX[N_NODES * DIM];
__device__ float g_EX[N_NODES * DIM];
__device__ float g_num[N_NODES * DIM];
__device__ float g_den[N_NODES * DIM];
__device__ float g_deg[N_NODES];
__device__ float g_hsum[DIM];
__device__ float g_hsq[DIM];
__device__ float g_esum[DIM];
__device__ float g_esq[DIM];

// ---------------- helpers ----------------------------------------------------
__device__ __forceinline__ void red_add_v4(float* addr, float a, float b, float c, float d) {
    asm volatile("red.global.add.v4.f32 [%0], {%1, %2, %3, %4};"
                 :: "l"(addr), "f"(a), "f"(b), "f"(c), "f"(d)
                 : "memory");
}

__device__ __forceinline__ uint32_t f2tf32(float x) {
    uint32_t r;
    asm("cvt.rna.tf32.f32 %0, %1;" : "=r"(r) : "f"(x));
    return r;
}

__device__ __forceinline__ void mma_tf32(float c[4],
                                         uint32_t a0, uint32_t a1, uint32_t a2, uint32_t a3,
                                         uint32_t b0, uint32_t b1) {
    asm volatile("mma.sync.aligned.m16n8k8.row.col.f32.tf32.tf32.f32 "
                 "{%0,%1,%2,%3},{%4,%5,%6,%7},{%8,%9},{%0,%1,%2,%3};"
                 : "+f"(c[0]), "+f"(c[1]), "+f"(c[2]), "+f"(c[3])
                 : "r"(a0), "r"(a1), "r"(a2), "r"(a3), "r"(b0), "r"(b1));
}

// ================================================================================
// TF32 tensor-core GEMM core: 64x128 tile, 256 threads, 8 warps arranged as
// 2 row-groups (wr: 32 rows) x 4 col-groups (wc: 32 cols). Warp tile 32x32:
// acc[2 m-halves][4 n-tiles][4]. Per 8-k step: 8 A-LDS + 8 B-LDS for 8 MMAs.
// ================================================================================
__device__ __forceinline__ void gemm_tc64(const float* __restrict__ A, const float* __restrict__ W,
                                          int rowBase, int M, float* As, float* Ws,
                                          float acc[2][4][4], int tid) {
    int lane = tid & 31, wid = tid >> 5;
    int wr = wid & 1, wc = wid >> 1;
    uint32_t* Asu = (uint32_t*)As;
    uint32_t* Wsu = (uint32_t*)Ws;

    #pragma unroll
    for (int h = 0; h < 2; h++)
        #pragma unroll
        for (int t = 0; t < 4; t++)
            #pragma unroll
            for (int j = 0; j < 4; j++) acc[h][t][j] = 0.f;

    int akl = lane & 3;
    int aro = lane >> 2;

    #pragma unroll
    for (int k0 = 0; k0 < 128; k0 += 32) {
        // stage A tile (64 x 32) with tf32 rounding: 512 float4 = 2/thread
        #pragma unroll
        for (int u = 0; u < 2; u++) {
            int idx = tid + u * 256;            // 0..511
            int r = idx >> 3;
            int c4 = (idx & 7) * 4;
            int gr = min(rowBase + r, M - 1);
            float4 v = *(const float4*)&A[(long)gr * 128 + k0 + c4];
            Asu[r * AS_STRIDE + c4 + 0] = f2tf32(v.x);
            Asu[r * AS_STRIDE + c4 + 1] = f2tf32(v.y);
            Asu[r * AS_STRIDE + c4 + 2] = f2tf32(v.z);
            Asu[r * AS_STRIDE + c4 + 3] = f2tf32(v.w);
        }
        // stage W tile (32 x 128): 1024 float4 = 4/thread
        #pragma unroll
        for (int u = 0; u < 4; u++) {
            int idx = tid + u * 256;
            int kk = idx >> 5;
            int c4 = (idx & 31) * 4;
            float4 v = *(const float4*)&W[(long)(k0 + kk) * 128 + c4];
            Wsu[kk * WS_STRIDE + c4 + 0] = f2tf32(v.x);
            Wsu[kk * WS_STRIDE + c4 + 1] = f2tf32(v.y);
            Wsu[kk * WS_STRIDE + c4 + 2] = f2tf32(v.z);
            Wsu[kk * WS_STRIDE + c4 + 3] = f2tf32(v.w);
        }
        __syncthreads();
        #pragma unroll
        for (int ks = 0; ks < 4; ks++) {
            int kb = ks * 8;
            uint32_t a[2][4];
            #pragma unroll
            for (int h = 0; h < 2; h++) {
                int r = wr * 32 + h * 16 + aro;
                a[h][0] = Asu[r * AS_STRIDE + kb + akl];
                a[h][1] = Asu[(r + 8) * AS_STRIDE + kb + akl];
                a[h][2] = Asu[r * AS_STRIDE + kb + 4 + akl];
                a[h][3] = Asu[(r + 8) * AS_STRIDE + kb + 4 + akl];
            }
            #pragma unroll
            for (int t = 0; t < 4; t++) {
                int cn = wc * 32 + t * 8 + aro;
                uint32_t b0 = Wsu[(kb + akl) * WS_STRIDE + cn];
                uint32_t b1 = Wsu[(kb + 4 + akl) * WS_STRIDE + cn];
                mma_tf32(acc[0][t], a[0][0], a[0][1], a[0][2], a[0][3], b0, b1);
                mma_tf32(acc[1][t], a[1][0], a[1][1], a[1][2], a[1][3], b0, b1);
            }
        }
        __syncthreads();
    }
}

// store the warp's rows belonging to [h32*32, h32*32+32) into Cs[32][CS_STRIDE]
__device__ __forceinline__ void store_half32(float* Cs, float acc[2][4][4], int h32, int tid) {
    int lane = tid & 31, wid = tid >> 5;
    int wr = wid & 1, wc = wid >> 1;
    if (wr == h32) {
        #pragma unroll
        for (int h = 0; h < 2; h++) {
            int lr = h * 16 + (lane >> 2);
            #pragma unroll
            for (int t = 0; t < 4; t++) {
                int c = wc * 32 + t * 8 + 2 * (lane & 3);
                *(float2*)&Cs[lr * CS_STRIDE + c]       = make_float2(acc[h][t][0], acc[h][t][1]);
                *(float2*)&Cs[(lr + 8) * CS_STRIDE + c] = make_float2(acc[h][t][2], acc[h][t][3]);
            }
        }
    }
}

// ---------------- zero scratch ------------------------------------------------
__global__ void zero_scratch(float4* num4, float4* den4, float* deg,
                             float* hsum, float* hsq, float* esum, float* esq) {
    int i = blockIdx.x * blockDim.x + threadIdx.x;   // exactly N*D/4 threads
    float4 z = make_float4(0.f, 0.f, 0.f, 0.f);
    num4[i] = z;
    den4[i] = z;
    if (i < N_NODES) deg[i] = 0.f;
    if (i < DIM) { hsum[i] = 0.f; hsq[i] = 0.f; esum[i] = 0.f; esq[i] = 0.f; }
}

// ---------------- degree ------------------------------------------------------
__global__ void deg_kernel(const int* __restrict__ dst, float* __restrict__ deg) {
    int i = blockIdx.x * blockDim.x + threadIdx.x;
    if (i < N_EDGES) atomicAdd(&deg[dst[i]], 1.f);
}

// ---------------- fused node GEMMs (tensor core) --------------------------------
__global__ __launch_bounds__(256, 3)
void gemm_bias(const float* __restrict__ A,
               const float* __restrict__ W0, const float* __restrict__ b0, float* __restrict__ o0,
               const float* __restrict__ W1, const float* __restrict__ b1, float* __restrict__ o1,
               const float* __restrict__ W2, const float* __restrict__ b2, float* __restrict__ o2,
               const float* __restrict__ W3, const float* __restrict__ b3, float* __restrict__ o3,
               int M) {
    __shared__ float smem[SMEM_FLOATS];
    float* As = smem;
    float* Ws = smem + BLK_M * AS_STRIDE;
    float* Cs = smem;   // alias, used after GEMM (32 x CS_STRIDE fits)

    const float *W, *bias;
    float* out;
    switch (blockIdx.y) {
        case 0:  W = W0; bias = b0; out = o0; break;
        case 1:  W = W1; bias = b1; out = o1; break;
        case 2:  W = W2; bias = b2; out = o2; break;
        default: W = W3; bias = b3; out = o3; break;
    }
    int tid = threadIdx.x;
    int rowBase = blockIdx.x * BLK_M;

    float acc[2][4][4];
    gemm_tc64(A, W, rowBase, M, As, Ws, acc, tid);

    #pragma unroll
    for (int h32 = 0; h32 < 2; h32++) {
        store_half32(Cs, acc, h32, tid);
        __syncthreads();
        int r = tid >> 3, q = tid & 7;
        int grow = rowBase + h32 * 32 + r;
        if (grow < M) {
            #pragma unroll
            for (int cb = 0; cb < 4; cb++) {
                int c = q * 16 + cb * 4;
                float4 v = *(float4*)&Cs[r * CS_STRIDE + c];
                float4 bb = __ldg((const float4*)&bias[c]);
                v.x += bb.x; v.y += bb.y; v.z += bb.z; v.w += bb.w;
                *(float4*)&out[(long)grow * 128 + c] = v;
            }
        }
        __syncthreads();
    }
}

// ---------------- fused edge kernel (tensor core) -------------------------------
__global__ __launch_bounds__(256, 3)
void edge_kernel(const float* __restrict__ EXin, const float* __restrict__ W,
                 const float* __restrict__ bias,
                 const int* __restrict__ src, const int* __restrict__ dst,
                 const float* __restrict__ sne,
                 const float* __restrict__ BX, const float* __restrict__ DXn,
                 const float* __restrict__ EXn,
                 float* __restrict__ num, float* __restrict__ den,
                 float* __restrict__ outE) {
    __shared__ float smem[SMEM_FLOATS];
    __shared__ int   s_src[BLK_M];
    __shared__ int   s_dst[BLK_M];
    __shared__ float s_sn[BLK_M];
    float* As = smem;
    float* Ws = smem + BLK_M * AS_STRIDE;
    float* Cs = smem;

    int tid = threadIdx.x;
    int rowBase = blockIdx.x * BLK_M;

    if (tid < BLK_M) {
        int e = min(rowBase + tid, N_EDGES - 1);
        s_src[tid] = src[e];
        s_dst[tid] = dst[e];
        s_sn[tid]  = sne[e];
    }

    float acc[2][4][4];
    gemm_tc64(EXin, W, rowBase, N_EDGES, As, Ws, acc, tid);

    #pragma unroll
    for (int h32 = 0; h32 < 2; h32++) {
        store_half32(Cs, acc, h32, tid);
        __syncthreads();
        int r = tid >> 3, q = tid & 7;
        long e = (long)rowBase + h32 * 32 + r;
        if (e < N_EDGES) {
            int sv = s_src[h32 * 32 + r];
            int dv = s_dst[h32 * 32 + r];
            float sn = s_sn[h32 * 32 + r];
            const float* dxp = &DXn[(long)sv * 128];
            const float* exp_ = &EXn[(long)dv * 128];
            const float* bxp = &BX[(long)sv * 128];
            float* np = &num[(long)dv * 128];
            float* dp = &den[(long)dv * 128];
            float* op = &outE[e * 128];
            #pragma unroll
            for (int cb = 0; cb < 4; cb++) {
                int c = q * 16 + cb * 4;
                float4 ce = *(float4*)&Cs[r * CS_STRIDE + c];
                float4 bb = __ldg((const float4*)&bias[c]);
                float4 dx = *(const float4*)&dxp[c];
                float4 ex = *(const float4*)&exp_[c];
                float4 bx = *(const float4*)&bxp[c];
                float ej[4] = {ce.x + bb.x + dx.x + ex.x,
                               ce.y + bb.y + dx.y + ex.y,
                               ce.z + bb.z + dx.z + ex.z,
                               ce.w + bb.w + dx.w + ex.w};
                float sg[4], nb[4];
                #pragma unroll
                for (int j = 0; j < 4; j++) sg[j] = 1.f / (1.f + __expf(-ej[j]));
                nb[0] = sg[0] * bx.x; nb[1] = sg[1] * bx.y;
                nb[2] = sg[2] * bx.z; nb[3] = sg[3] * bx.w;
                // streaming store: keep L2 for gathers/atomics
                __stcs((float4*)&op[c], make_float4(ej[0] * sn, ej[1] * sn,
                                                    ej[2] * sn, ej[3] * sn));
                red_add_v4(np + c, nb[0], nb[1], nb[2], nb[3]);
                red_add_v4(dp + c, sg[0], sg[1], sg[2], sg[3]);
            }
        }
        __syncthreads();
    }
}

// ---------------- E column stats (sum, sumsq) over outE --------------------------
__global__ void estats_kernel(const float4* __restrict__ E4,
                              float* __restrict__ esum, float* __restrict__ esq) {
    __shared__ float sm1[128];
    __shared__ float sm2[128];
    int tid = threadIdx.x;
    if (tid < 128) { sm1[tid] = 0.f; sm2[tid] = 0.f; }
    __syncthreads();

    int c4 = tid & 31;
    int rlane = tid >> 5;
    long totalRows = N_EDGES;
    long rstep = (long)gridDim.x * 8;

    float4 s1 = make_float4(0.f, 0.f, 0.f, 0.f);
    float4 s2 = make_float4(0.f, 0.f, 0.f, 0.f);
    for (long r = (long)blockIdx.x * 8 + rlane; r < totalRows; r += rstep) {
        float4 v = __ldcs(&E4[r * 32 + c4]);
        s1.x += v.x; s1.y += v.y; s1.z += v.z; s1.w += v.w;
        s2.x += v.x * v.x; s2.y += v.y * v.y; s2.z += v.z * v.z; s2.w += v.w * v.w;
    }
    atomicAdd(&sm1[c4 * 4 + 0], s1.x);
    atomicAdd(&sm1[c4 * 4 + 1], s1.y);
    atomicAdd(&sm1[c4 * 4 + 2], s1.z);
    atomicAdd(&sm1[c4 * 4 + 3], s1.w);
    atomicAdd(&sm2[c4 * 4 + 0], s2.x);
    atomicAdd(&sm2[c4 * 4 + 1], s2.y);
    atomicAdd(&sm2[c4 * 4 + 2], s2.z);
    atomicAdd(&sm2[c4 * 4 + 3], s2.w);
    __syncthreads();
    if (tid < 128) atomicAdd(&esum[tid], sm1[tid]);
    else           atomicAdd(&esq[tid - 128], sm2[tid - 128]);
}

// ---------------- node pre-BN: Hpre = gate-combine * snorm_n + stats ------------
__global__ void node_pre(const float* __restrict__ X, const float* __restrict__ AX,
                         const float* __restrict__ num, const float* __restrict__ den,
                         const float* __restrict__ deg, const float* __restrict__ snorm_n,
                         float* __restrict__ outH,
                         float* __restrict__ hsum, float* __restrict__ hsq) {
    __shared__ float sm1[128];
    __shared__ float sm2[128];
    int tid = threadIdx.x;
    if (tid < 128) { sm1[tid] = 0.f; sm2[tid] = 0.f; }
    __syncthreads();

    int c = tid & 127;
    int half = tid >> 7;
    int rBase = blockIdx.x * 64;
    int rEnd = min(rBase + 64, N_NODES);

    float s1 = 0.f, s2 = 0.f;
    for (int r = rBase + half; r < rEnd; r += 2) {
        float dg = deg[r];
        float sn = snorm_n[r];
        long idx = (long)r * 128 + c;
        float hv;
        if (dg > 0.f) {
            float dn = den[idx];
            float qv = (dn > 0.f) ? (num[idx] / dn) : 0.f;
            hv = AX[idx] + qv;
        } else {
            hv = X[idx];
        }
        hv *= sn;
        outH[idx] = hv;
        s1 += hv;
        s2 += hv * hv;
    }
    atomicAdd(&sm1[c], s1);
    atomicAdd(&sm2[c], s2);
    __syncthreads();
    if (tid < 128) atomicAdd(&hsum[tid], sm1[tid]);
    else           atomicAdd(&hsq[tid - 128], sm2[tid - 128]);
}

// ---------------- finalize: out = base + relu(BN(pre)) (in-place over pre) ------
__global__ void finalize_bn(const float* __restrict__ base, float* __restrict__ pre,
                            const float* __restrict__ sum, const float* __restrict__ sq,
                            const float* __restrict__ gamma, const float* __restrict__ beta,
                            long total4, float invn) {
    long i = (long)blockIdx.x * blockDim.x + threadIdx.x;
    if (i >= total4) return;
    int c4 = (int)(i & 31) * 4;
    float4 v  = __ldcs(&((const float4*)pre)[i]);
    float4 xv = __ldcs(&((const float4*)base)[i]);
    float vv[4] = {v.x, v.y, v.z, v.w};
    float xx[4] = {xv.x, xv.y, xv.z, xv.w};
    float oo[4];
    #pragma unroll
    for (int j = 0; j < 4; j++) {
        int c = c4 + j;
        float m   = __ldg(&sum[c]) * invn;
        float var = __ldg(&sq[c]) * invn - m * m;
        float rs  = rsqrtf(var + BN_EPS);
        float t = (vv[j] - m) * rs * __ldg(&gamma[c]) + __ldg(&beta[c]);
        oo[j] = xx[j] + fmaxf(t, 0.f);
    }
    __stcs(&((float4*)pre)[i], make_float4(oo[0], oo[1], oo[2], oo[3]));
}

// ---------------- launch --------------------------------------------------------
extern "C" void kernel_launch(void* const* d_in, const int* in_sizes, int n_in,
                              void* d_out, int out_size) {
    const float* X       = (const float*)d_in[0];
    const float* E_X     = (const float*)d_in[1];
    const int*   src     = (const int*)  d_in[2];
    const int*   dst     = (const int*)  d_in[3];
    const float* snorm_n = (const float*)d_in[4];
    const float* snorm_e = (const float*)d_in[5];
    const float* WA = (const float*)d_in[6];
    const float* bA = (const float*)d_in[7];
    const float* WB = (const float*)d_in[8];
    const float* bB = (const float*)d_in[9];
    const float* WC = (const float*)d_in[10];
    const float* bC = (const float*)d_in[11];
    const float* WD = (const float*)d_in[12];
    const float* bD = (const float*)d_in[13];
    const float* WE = (const float*)d_in[14];
    const float* bE = (const float*)d_in[15];
    const float* gamma_h = (const float*)d_in[16];
    const float* beta_h  = (const float*)d_in[17];
    const float* gamma_e = (const float*)d_in[18];
    const float* beta_e  = (const float*)d_in[19];

    float* out  = (float*)d_out;
    float* outH = out;
    float* outE = out + (long)N_NODES * DIM;

    float *pAX, *pBX, *pDX, *pEX, *pnum, *pden, *pdeg;
    float *phsum, *phsq, *pesum, *pesq;
    cudaGetSymbolAddress((void**)&pAX, g_AX);
    cudaGetSymbolAddress((void**)&pBX, g_BX);
    cudaGetSymbolAddress((void**)&pDX, g_DX);
    cudaGetSymbolAddress((void**)&pEX, g_EX);
    cudaGetSymbolAddress((void**)&pnum, g_num);
    cudaGetSymbolAddress((void**)&pden, g_den);
    cudaGetSymbolAddress((void**)&pdeg, g_deg);
    cudaGetSymbolAddress((void**)&phsum, g_hsum);
    cudaGetSymbolAddress((void**)&phsq, g_hsq);
    cudaGetSymbolAddress((void**)&pesum, g_esum);
    cudaGetSymbolAddress((void**)&pesq, g_esq);

    // 1. zero scratch
    zero_scratch<<<6250, 256>>>((float4*)pnum, (float4*)pden, pdeg,
                                phsum, phsq, pesum, pesq);

    // 2. node GEMMs (tensor core, fused: grid.y selects A/B/D/E weights)
    dim3 ngrid((N_NODES + BLK_M - 1) / BLK_M, 4);   // 782 x 4
    gemm_bias<<<ngrid, 256>>>(X,
                              WA, bA, pAX,
                              WB, bB, pBX,
                              WD, bD, pDX,
                              WE, bE, pEX,
                              N_NODES);

    // 3. degrees
    deg_kernel<<<(N_EDGES + 255) / 256, 256>>>(dst, pdeg);

    // 4. fused edge kernel (CE GEMM + message + gated scatter)
    int edgeBlocks = (N_EDGES + BLK_M - 1) / BLK_M;   // 7813
    edge_kernel<<<edgeBlocks, 256>>>(E_X, WC, bC, src, dst, snorm_e,
                                     pBX, pDX, pEX, pnum, pden, outE);

    // 5. E column stats
    estats_kernel<<<1184, 256>>>((const float4*)outE, pesum, pesq);

    // 6. node combine + H stats
    node_pre<<<(N_NODES + 63) / 64, 256>>>(X, pAX, pnum, pden, pdeg, snorm_n,
                                           outH, phsum, phsq);

    // 7. finalize H: out = X + relu(BN(Hpre))
    long h4 = (long)N_NODES * DIM / 4;       // 1.6M
    finalize_bn<<<(int)((h4 + 255) / 256), 256>>>(X, outH, phsum, phsq,
                                                  gamma_h, beta_h, h4, 1.f / N_NODES);

    // 8. finalize E: out = E_X + relu(BN(Epre))
    long e4 = (long)N_EDGES * DIM / 4;       // 16M
    finalize_bn<<<(int)((e4 + 255) / 256), 256>>>(E_X, outE, pesum, pesq,
                                                  gamma_e, beta_e, e4, 1.f / N_EDGES);
}